// round 10
// baseline (speedup 1.0000x reference)
#include <cuda_runtime.h>

// Problem constants
#define BN_  4
#define C_   256
#define NPX_ 4096    // 64*64
#define O_   64
#define G_   16
#define GC_  16
#define KK_  49      // 7*7
#define KPAD 56      // padded kernel count

typedef unsigned long long ull;
typedef unsigned int uint;

// --------- scratch (allocation-free: __device__ globals) ----------
__device__ __align__(16) float g_thi[BN_ * NPX_ * O_];   // t tf32-hi, [b][px][o]
__device__ __align__(16) float g_tlo[BN_ * NPX_ * O_];   // t tf32-lo residual
__device__ __align__(16) float g_w1t[C_ * O_];           // [c][o], BN-folded
__device__ float g_b1[O_];
__device__ __align__(16) float g_w2hi[G_ * O_ * KPAD];   // [g][o][k] tf32-hi
__device__ __align__(16) float g_w2lo[G_ * O_ * KPAD];   // [g][o][k] tf32-lo
__device__ __align__(16) float g_wt[(size_t)BN_ * 64 * G_ * KPAD * 64]; // [b][tile][g][k][px]

// --------- f32x2 helpers ----------
__device__ __forceinline__ ull pk(float a, float b) {
    ull r; asm("mov.b64 %0,{%1,%2};" : "=l"(r) : "f"(a), "f"(b)); return r;
}
__device__ __forceinline__ ull dupf(float a) {
    ull r; asm("mov.b64 %0,{%1,%1};" : "=l"(r) : "f"(a)); return r;
}
__device__ __forceinline__ void fma2(ull& d, ull a, ull b) {
    asm("fma.rn.f32x2 %0,%1,%2,%0;" : "+l"(d) : "l"(a), "l"(b));
}
__device__ __forceinline__ void unpk(ull v, float& a, float& b) {
    asm("mov.b64 {%0,%1},%2;" : "=f"(a), "=f"(b) : "l"(v));
}
__device__ __forceinline__ float tf32_rna(float a) {
    uint u; asm("cvt.rna.tf32.f32 %0, %1;" : "=r"(u) : "f"(a));
    return __uint_as_float(u);
}
__device__ __forceinline__ void mma_tf32(float& c0, float& c1, float& c2, float& c3,
                                         uint a0, uint a1, uint a2, uint a3,
                                         uint b0, uint b1) {
    asm volatile("mma.sync.aligned.m16n8k8.row.col.f32.tf32.tf32.f32 "
                 "{%0,%1,%2,%3}, {%4,%5,%6,%7}, {%8,%9}, {%0,%1,%2,%3};"
                 : "+f"(c0), "+f"(c1), "+f"(c2), "+f"(c3)
                 : "r"(a0), "r"(a1), "r"(a2), "r"(a3), "r"(b0), "r"(b1));
}

// =================================================================
// Prep: BN-fold+transpose w1; split-transpose w2 -> [g][o][k] hi/lo.
// =================================================================
__global__ __launch_bounds__(256) void prep_kernel(const float* __restrict__ w1,
                                                   const float* __restrict__ gamma,
                                                   const float* __restrict__ beta,
                                                   const float* __restrict__ mean,
                                                   const float* __restrict__ var,
                                                   const float* __restrict__ w2) {
    int tid = blockIdx.x * 256 + threadIdx.x;
    int nthr = gridDim.x * 256;

    for (int i = tid; i < C_ * O_; i += nthr) {
        int c = i >> 6, o = i & 63;
        float sc = gamma[o] * rsqrtf(var[o] + 1e-5f);
        g_w1t[i] = w1[(size_t)o * C_ + c] * sc;
    }
    if (tid < O_) {
        float sc = gamma[tid] * rsqrtf(var[tid] + 1e-5f);
        g_b1[tid] = beta[tid] - mean[tid] * sc;
    }
    for (int i = tid; i < G_ * KK_ * O_; i += nthr) {
        int o = i & 63;
        int gk = i >> 6;            // g*49 + k
        int g = gk / KK_, k = gk - g * KK_;
        float v = w2[i];
        float hi = tf32_rna(v);
        float lo = tf32_rna(v - hi);
        size_t idx = ((size_t)(g * O_ + o)) * KPAD + k;
        g_w2hi[idx] = hi;
        g_w2lo[idx] = lo;
    }
    for (int i = tid; i < G_ * O_ * (KPAD - KK_); i += nthr) {
        int kk = i % (KPAD - KK_);
        int go = i / (KPAD - KK_);
        g_w2hi[(size_t)go * KPAD + KK_ + kk] = 0.f;
        g_w2lo[(size_t)go * KPAD + KK_ + kk] = 0.f;
    }
}

// =================================================================
// conv1: t = relu(w1t^T x + b1), written as tf32 hi/lo pair.
// Block: 128 threads, 32 px x 64 o, grid 512. Thread: 2px x 8o.
// =================================================================
#define WS1 68
__global__ __launch_bounds__(128) void conv1_kernel(const float* __restrict__ x) {
    __shared__ __align__(16) float xs[32 * 32];   // [c][px]
    __shared__ __align__(16) float ws[32 * WS1];  // [c][o] (+pad)

    int tid = threadIdx.x;
    int bpx0 = blockIdx.x * 32;
    const float* xb = x + (size_t)(bpx0 / NPX_) * C_ * NPX_ + (bpx0 % NPX_);

    int to = tid & 7, tp = tid >> 3;
    int p0 = tp * 2, o0 = to * 8;

    ull acc0[4] = {0, 0, 0, 0};
    ull acc1[4] = {0, 0, 0, 0};

    for (int cc = 0; cc < C_; cc += 32) {
        __syncthreads();
#pragma unroll
        for (int i = 0; i < 8; i++) {
            int idx = tid + i * 128;
            int c = idx >> 5, low = idx & 31;
            xs[c * 32 + low] = xb[(size_t)(cc + c) * NPX_ + low];
        }
#pragma unroll
        for (int i = 0; i < 16; i++) {
            int idx = tid + i * 128;
            int c = idx >> 6, o = idx & 63;
            ws[c * WS1 + o] = g_w1t[(cc + c) * O_ + o];
        }
        __syncthreads();
#pragma unroll
        for (int c = 0; c < 32; c++) {
            float2 xv = *(const float2*)&xs[c * 32 + p0];
            ull x0d = dupf(xv.x), x1d = dupf(xv.y);
            ulonglong2 wA = *(const ulonglong2*)&ws[c * WS1 + o0];
            ulonglong2 wB = *(const ulonglong2*)&ws[c * WS1 + o0 + 4];
            fma2(acc0[0], wA.x, x0d); fma2(acc0[1], wA.y, x0d);
            fma2(acc0[2], wB.x, x0d); fma2(acc0[3], wB.y, x0d);
            fma2(acc1[0], wA.x, x1d); fma2(acc1[1], wA.y, x1d);
            fma2(acc1[2], wB.x, x1d); fma2(acc1[3], wB.y, x1d);
        }
    }

#pragma unroll
    for (int p = 0; p < 2; p++) {
        ull* acc = p ? acc1 : acc0;
        float vh[8], vl[8];
#pragma unroll
        for (int j = 0; j < 4; j++) {
            float a, b;
            unpk(acc[j], a, b);
            float va = fmaxf(a + g_b1[o0 + 2 * j], 0.f);
            float vb = fmaxf(b + g_b1[o0 + 2 * j + 1], 0.f);
            float ha = tf32_rna(va), hb = tf32_rna(vb);
            vh[2 * j] = ha;             vh[2 * j + 1] = hb;
            vl[2 * j] = tf32_rna(va - ha); vl[2 * j + 1] = tf32_rna(vb - hb);
        }
        size_t base = (size_t)(bpx0 + p0 + p) * O_ + o0;
        *(float4*)&g_thi[base]     = make_float4(vh[0], vh[1], vh[2], vh[3]);
        *(float4*)&g_thi[base + 4] = make_float4(vh[4], vh[5], vh[6], vh[7]);
        *(float4*)&g_tlo[base]     = make_float4(vl[0], vl[1], vl[2], vl[3]);
        *(float4*)&g_tlo[base + 4] = make_float4(vl[4], vl[5], vl[6], vl[7]);
    }
}

// =================================================================
// conv2 via tf32 tensor cores (3xTF32 split): wt = t @ w2^T + b2.
// Grid (b,tile,g-quarter)=1024, 128 thr (4 warps), NO smem/syncs.
// Warp: m16 (16 px of the 8x8 tile) x [4 groups x 56 k], K=64.
// A frags persist in regs; B frags via L1-cached LDG.
// =================================================================
__global__ __launch_bounds__(128) void conv2_mma(const float* __restrict__ b2) {
    int tid = threadIdx.x, bid = blockIdx.x;
    int gq = bid & 3;
    int tile = (bid >> 2) & 63;
    int b = bid >> 8;
    int y0 = (tile >> 3) * 8, x0 = (tile & 7) * 8;

    int wid = tid >> 5, lane = tid & 31;
    int gid = lane >> 2, tig = lane & 3;
    int m = wid * 16;
    int pxl0 = m + gid, pxl1 = m + gid + 8;
    int gpx0 = (y0 + (pxl0 >> 3)) * 64 + x0 + (pxl0 & 7);
    int gpx1 = (y0 + (pxl1 >> 3)) * 64 + x0 + (pxl1 & 7);

    const uint* th = (const uint*)g_thi + (size_t)b * NPX_ * O_;
    const uint* tl = (const uint*)g_tlo + (size_t)b * NPX_ * O_;

    // A fragments (row=px, col=o): a0 (px0,o+tig) a1 (px1,o+tig) a2 (px0,o+tig+4) a3 (px1,o+tig+4)
    uint ah[8][4], al[8][4];
#pragma unroll
    for (int kt = 0; kt < 8; kt++) {
        int o0 = kt * 8 + tig, o1 = o0 + 4;
        ah[kt][0] = th[gpx0 * 64 + o0]; ah[kt][1] = th[gpx1 * 64 + o0];
        ah[kt][2] = th[gpx0 * 64 + o1]; ah[kt][3] = th[gpx1 * 64 + o1];
        al[kt][0] = tl[gpx0 * 64 + o0]; al[kt][1] = tl[gpx1 * 64 + o0];
        al[kt][2] = tl[gpx0 * 64 + o1]; al[kt][3] = tl[gpx1 * 64 + o1];
    }

#pragma unroll 1
    for (int gg = 0; gg < 4; gg++) {
        int g = gq * 4 + gg;
        const uint* wh = (const uint*)g_w2hi + (size_t)g * O_ * KPAD;
        const uint* wl = (const uint*)g_w2lo + (size_t)g * O_ * KPAD;
        float* wout = g_wt + (((size_t)(b * 64 + tile)) * G_ + g) * KPAD * 64;
#pragma unroll 1
        for (int nt = 0; nt < 7; nt++) {
            int nb = nt * 8;
            int k0 = nb + 2 * tig, k1 = k0 + 1;
            float bias0 = (k0 < KK_) ? b2[g * KK_ + k0] : 0.f;
            float bias1 = (k1 < KK_) ? b2[g * KK_ + k1] : 0.f;
            float c0 = bias0, c1 = bias1, c2 = bias0, c3 = bias1;
#pragma unroll
            for (int kt = 0; kt < 8; kt++) {
                int o0 = kt * 8 + tig, o1 = o0 + 4;
                // B frags (row=o within k-step, col=k): b0 (o+tig, k+gid) b1 (o+tig+4, k+gid)
                uint b0h = wh[o0 * KPAD + nb + gid], b1h = wh[o1 * KPAD + nb + gid];
                uint b0l = wl[o0 * KPAD + nb + gid], b1l = wl[o1 * KPAD + nb + gid];
                mma_tf32(c0, c1, c2, c3, ah[kt][0], ah[kt][1], ah[kt][2], ah[kt][3], b0h, b1h);
                mma_tf32(c0, c1, c2, c3, al[kt][0], al[kt][1], al[kt][2], al[kt][3], b0h, b1h);
                mma_tf32(c0, c1, c2, c3, ah[kt][0], ah[kt][1], ah[kt][2], ah[kt][3], b0l, b1l);
            }
            // C frags: c0 (px0,k0) c1 (px0,k1) c2 (px1,k0) c3 (px1,k1)
            wout[k0 * 64 + pxl0] = c0; wout[k1 * 64 + pxl0] = c1;
            wout[k0 * 64 + pxl1] = c2; wout[k1 * 64 + pxl1] = c3;
        }
    }
}

// =================================================================
// Involution-only kernel: grid (b,tile,gs4)=1024, 256 thr.
// smem = xg (14.25KB) + wt stage (12.25KB) = 26.5KB -> occupancy 8.
// =================================================================
#define XG_CH 228              // >= 13*16+14=222 footprint, ==4 mod 32

__global__ __launch_bounds__(256) void inv_kernel(const float* __restrict__ x,
                                                  float* __restrict__ out) {
    __shared__ __align__(16) float xg[16 * XG_CH];
    __shared__ __align__(16) float wt_s[KK_ * 64];

    int tid = threadIdx.x;
    int bid = blockIdx.x;
    int gs = bid & 3;
    int tile = (bid >> 2) & 63;
    int b = bid >> 8;
    int y0 = (tile >> 3) * 8, x0 = (tile & 7) * 8;
    const float* xb = x + (size_t)b * C_ * NPX_;

    int ci = tid & 15, pxq = tid >> 4;
    int px0 = pxq * 4;
    int yloc = pxq >> 1, x0loc = (pxq & 1) * 4;

#pragma unroll 1
    for (int gi = 0; gi < 4; gi++) {
        int g = gs * 4 + gi;
        __syncthreads();

        // stage x group halo (14x14 per channel, zero-padded)
        for (int idx = tid; idx < 16 * 196; idx += 256) {
            int c = idx / 196, rem = idx - c * 196;
            int rr = rem / 14, xx = rem - rr * 14;
            int gy = y0 + rr - 3, gx = x0 + xx - 3;
            float v = 0.f;
            if (gy >= 0 && gy < 64 && gx >= 0 && gx < 64)
                v = xb[(size_t)(g * GC_ + c) * NPX_ + gy * 64 + gx];
            xg[c * XG_CH + rr * 16 + xx] = v;
        }
        // stage wt (contiguous [49][64] slab)
        {
            const float* src = g_wt + (((size_t)(b * 64 + tile)) * G_ + g) * KPAD * 64;
            for (int idx = tid; idx < KK_ * 64; idx += 256)
                wt_s[idx] = src[idx];
        }
        __syncthreads();

        // involution: 4 adjacent-x pixels x 1 channel per thread
        ull acc01 = 0ull, acc23 = 0ull;
        const float* xgc = xg + ci * XG_CH + yloc * 16 + x0loc;
        const float* wtp = wt_s + px0;
#pragma unroll
        for (int ky = 0; ky < 7; ky++) {
            const float* rowp = xgc + ky * 16;
            float4 rA = *(const float4*)rowp;
            float4 rB = *(const float4*)(rowp + 4);
            float2 rC = *(const float2*)(rowp + 8);
            float xr[10] = {rA.x, rA.y, rA.z, rA.w,
                            rB.x, rB.y, rB.z, rB.w,
                            rC.x, rC.y};
            ull xp[9];
#pragma unroll
            for (int j = 0; j < 9; j++) xp[j] = pk(xr[j], xr[j + 1]);
#pragma unroll
            for (int kx = 0; kx < 7; kx++) {
                ulonglong2 wq = *(const ulonglong2*)(wtp + (ky * 7 + kx) * 64);
                fma2(acc01, wq.x, xp[kx]);
                fma2(acc23, wq.y, xp[kx + 2]);
            }
        }
        float v0, v1, v2, v3;
        unpk(acc01, v0, v1);
        unpk(acc23, v2, v3);
        int gy = y0 + yloc, gx = x0 + x0loc;
        *(float4*)&out[((size_t)b * C_ + g * GC_ + ci) * NPX_ + gy * 64 + gx] =
            make_float4(v0, v1, v2, v3);
    }
}

// =================================================================
extern "C" void kernel_launch(void* const* d_in, const int* in_sizes, int n_in,
                              void* d_out, int out_size) {
    const float* x     = (const float*)d_in[0];
    const float* w1    = (const float*)d_in[1];
    const float* gamma = (const float*)d_in[2];
    const float* beta  = (const float*)d_in[3];
    const float* mean  = (const float*)d_in[4];
    const float* var   = (const float*)d_in[5];
    const float* w2    = (const float*)d_in[6];
    const float* b2    = (const float*)d_in[7];
    float* out = (float*)d_out;

    prep_kernel<<<224, 256>>>(w1, gamma, beta, mean, var, w2);
    conv1_kernel<<<BN_ * NPX_ / 32, 128>>>(x);
    conv2_mma<<<BN_ * 64 * 4, 128>>>(b2);
    inv_kernel<<<BN_ * 64 * 4, 256>>>(x, out);
}

// round 11
// speedup vs baseline: 1.4433x; 1.4433x over previous
#include <cuda_runtime.h>

// Problem constants
#define BN_  4
#define C_   256
#define NPX_ 4096    // 64*64
#define O_   64
#define G_   16
#define GC_  16
#define KK_  49      // 7*7
#define KPAD 56      // padded kernel count

typedef unsigned long long ull;

// --------- scratch (allocation-free: __device__ globals) ----------
__device__ __align__(16) float g_t[BN_ * NPX_ * O_];     // t, [b][px][o], 4 MB
__device__ __align__(16) float g_w1t[C_ * O_];           // [c][o], BN-folded
__device__ float g_b1[O_];
__device__ __align__(16) float g_w2t[G_ * O_ * KPAD];    // [g][o][k], zero-padded
__device__ __align__(16) float g_wt[(size_t)BN_ * 64 * G_ * KK_ * 64]; // [b][tile][g][k][px]

// --------- f32x2 helpers (Blackwell packed fp32) ----------
__device__ __forceinline__ ull pk(float a, float b) {
    ull r; asm("mov.b64 %0,{%1,%2};" : "=l"(r) : "f"(a), "f"(b)); return r;
}
__device__ __forceinline__ ull dupf(float a) {
    ull r; asm("mov.b64 %0,{%1,%1};" : "=l"(r) : "f"(a)); return r;
}
__device__ __forceinline__ void fma2(ull& d, ull a, ull b) {
    asm("fma.rn.f32x2 %0,%1,%2,%0;" : "+l"(d) : "l"(a), "l"(b));
}
__device__ __forceinline__ void unpk(ull v, float& a, float& b) {
    asm("mov.b64 {%0,%1},%2;" : "=f"(a), "=f"(b) : "l"(v));
}

// =================================================================
// Prep: BN-fold + transpose w1 -> [c][o]; transpose w2 -> [g][o][k].
// =================================================================
__global__ __launch_bounds__(256) void prep_kernel(const float* __restrict__ w1,
                                                   const float* __restrict__ gamma,
                                                   const float* __restrict__ beta,
                                                   const float* __restrict__ mean,
                                                   const float* __restrict__ var,
                                                   const float* __restrict__ w2) {
    int tid = blockIdx.x * 256 + threadIdx.x;
    int nthr = gridDim.x * 256;

    for (int i = tid; i < C_ * O_; i += nthr) {
        int c = i >> 6, o = i & 63;
        float sc = gamma[o] * rsqrtf(var[o] + 1e-5f);
        g_w1t[i] = w1[(size_t)o * C_ + c] * sc;
    }
    if (tid < O_) {
        float sc = gamma[tid] * rsqrtf(var[tid] + 1e-5f);
        g_b1[tid] = beta[tid] - mean[tid] * sc;
    }
    for (int i = tid; i < G_ * KK_ * O_; i += nthr) {
        int o = i & 63;
        int gk = i >> 6;            // g*49 + k
        int g = gk / KK_, k = gk - g * KK_;
        g_w2t[((size_t)(g * O_ + o)) * KPAD + k] = w2[i];
    }
    for (int i = tid; i < G_ * O_ * (KPAD - KK_); i += nthr) {
        int kk = i % (KPAD - KK_);
        int go = i / (KPAD - KK_);
        g_w2t[(size_t)go * KPAD + KK_ + kk] = 0.f;
    }
}

// =================================================================
// conv1: t[bpx][o] = relu(sum_c w1t[c][o]*x + b1[o])
// Block: 128 threads, 32 px x 64 o, grid 512. Thread: 2px x 8o.
// =================================================================
#define WS1 68
__global__ __launch_bounds__(128) void conv1_kernel(const float* __restrict__ x) {
    __shared__ __align__(16) float xs[32 * 32];   // [c][px]
    __shared__ __align__(16) float ws[32 * WS1];  // [c][o] (+pad)

    int tid = threadIdx.x;
    int bpx0 = blockIdx.x * 32;
    const float* xb = x + (size_t)(bpx0 / NPX_) * C_ * NPX_ + (bpx0 % NPX_);

    int to = tid & 7, tp = tid >> 3;
    int p0 = tp * 2, o0 = to * 8;

    ull acc0[4] = {0, 0, 0, 0};
    ull acc1[4] = {0, 0, 0, 0};

    for (int cc = 0; cc < C_; cc += 32) {
        __syncthreads();
#pragma unroll
        for (int i = 0; i < 8; i++) {
            int idx = tid + i * 128;
            int c = idx >> 5, low = idx & 31;
            xs[c * 32 + low] = xb[(size_t)(cc + c) * NPX_ + low];
        }
#pragma unroll
        for (int i = 0; i < 16; i++) {
            int idx = tid + i * 128;
            int c = idx >> 6, o = idx & 63;
            ws[c * WS1 + o] = g_w1t[(cc + c) * O_ + o];
        }
        __syncthreads();
#pragma unroll
        for (int c = 0; c < 32; c++) {
            float2 xv = *(const float2*)&xs[c * 32 + p0];
            ull x0d = dupf(xv.x), x1d = dupf(xv.y);
            ulonglong2 wA = *(const ulonglong2*)&ws[c * WS1 + o0];
            ulonglong2 wB = *(const ulonglong2*)&ws[c * WS1 + o0 + 4];
            fma2(acc0[0], wA.x, x0d); fma2(acc0[1], wA.y, x0d);
            fma2(acc0[2], wB.x, x0d); fma2(acc0[3], wB.y, x0d);
            fma2(acc1[0], wA.x, x1d); fma2(acc1[1], wA.y, x1d);
            fma2(acc1[2], wB.x, x1d); fma2(acc1[3], wB.y, x1d);
        }
    }

#pragma unroll
    for (int p = 0; p < 2; p++) {
        ull* acc = p ? acc1 : acc0;
        float v[8];
#pragma unroll
        for (int j = 0; j < 4; j++) {
            float a, b;
            unpk(acc[j], a, b);
            v[2 * j]     = fmaxf(a + g_b1[o0 + 2 * j], 0.f);
            v[2 * j + 1] = fmaxf(b + g_b1[o0 + 2 * j + 1], 0.f);
        }
        float* dst = &g_t[(size_t)(bpx0 + p0 + p) * O_ + o0];
        *(float4*)dst       = make_float4(v[0], v[1], v[2], v[3]);
        *(float4*)(dst + 4) = make_float4(v[4], v[5], v[6], v[7]);
    }
}

// =================================================================
// conv2 standalone: wt[b][tile][g][k][px] = sum_o w2[g][o][k]*t[px][o] + b2.
// Grid (b,tile,gq4)=1024, 256 thr, 4 groups/block.
// smem = t_s (16.6KB) + w2s (14.3KB) = 31KB -> occ 7.
// Output STG coalesced (lanes cover contiguous px).
// =================================================================
#define TS_STRIDE 65
__global__ __launch_bounds__(256) void conv2_kernel(const float* __restrict__ b2) {
    __shared__ __align__(16) float t_s[64 * TS_STRIDE];
    __shared__ __align__(16) float w2s[64 * KPAD];

    int tid = threadIdx.x;
    int bid = blockIdx.x;
    int gq = bid & 3;
    int tile = (bid >> 2) & 63;
    int b = bid >> 8;
    int y0 = (tile >> 3) * 8, x0 = (tile & 7) * 8;

    // stage t tile (64 px x 64 o)
#pragma unroll
    for (int i = 0; i < 16; i++) {
        int idx = tid + i * 256;
        int pxl = idx >> 6, o = idx & 63;
        int r = pxl >> 3, cx = pxl & 7;
        t_s[pxl * TS_STRIDE + o] =
            g_t[((size_t)b * NPX_ + (y0 + r) * 64 + (x0 + cx)) * O_ + o];
    }

    int kq = tid >> 5, pq = tid & 31;

#pragma unroll 1
    for (int gi = 0; gi < 4; gi++) {
        int g = gq * 4 + gi;
        __syncthreads();   // prior compute done with w2s (and t_s staged, gi==0)
        {
            const float* src = g_w2t + (size_t)g * O_ * KPAD;
#pragma unroll
            for (int i = 0; i < 14; i++)
                w2s[tid + i * 256] = src[tid + i * 256];
        }
        __syncthreads();

        if (kq < 7) {
            int k0 = kq * 8;
            ull accA[4], accB[4];
#pragma unroll
            for (int j = 0; j < 4; j++) {
                int ka = k0 + 2 * j, kb = ka + 1;
                float ba = (ka < KK_) ? b2[g * KK_ + ka] : 0.f;
                float bb = (kb < KK_) ? b2[g * KK_ + kb] : 0.f;
                accA[j] = pk(ba, bb);
                accB[j] = accA[j];
            }
            const float* w2p = w2s + k0;
            const float* tp0 = t_s + pq * TS_STRIDE;
            const float* tp1 = t_s + (pq + 32) * TS_STRIDE;
#pragma unroll 8
            for (int o = 0; o < 64; o++) {
                ulonglong2 w01 = *(const ulonglong2*)(w2p + o * KPAD);
                ulonglong2 w23 = *(const ulonglong2*)(w2p + o * KPAD + 4);
                ull da = dupf(tp0[o]);
                ull db = dupf(tp1[o]);
                fma2(accA[0], w01.x, da); fma2(accA[1], w01.y, da);
                fma2(accA[2], w23.x, da); fma2(accA[3], w23.y, da);
                fma2(accB[0], w01.x, db); fma2(accB[1], w01.y, db);
                fma2(accB[2], w23.x, db); fma2(accB[3], w23.y, db);
            }
            float* wout = g_wt + (((size_t)(b * 64 + tile)) * G_ + g) * KK_ * 64;
#pragma unroll
            for (int j = 0; j < 4; j++) {
                int ka = k0 + 2 * j, kb = ka + 1;
                float a0, a1, b0, b1;
                unpk(accA[j], a0, a1);
                unpk(accB[j], b0, b1);
                if (ka < KK_) {
                    wout[ka * 64 + pq]      = a0;
                    wout[ka * 64 + pq + 32] = b0;
                }
                if (kb < KK_) {
                    wout[kb * 64 + pq]      = a1;
                    wout[kb * 64 + pq + 32] = b1;
                }
            }
        }
    }
}

// =================================================================
// Involution-only: grid (b,tile,gs4)=1024, 256 thr, 4 groups/block.
// smem = xg (14.6KB) + wt stage (12.5KB) = 27.1KB -> occ 8.
// Halo staging is division-free (14 straight-line iterations).
// =================================================================
#define XG_CH 228              // >= 13*16+14=222 footprint, ==4 mod 32

__global__ __launch_bounds__(256) void inv_kernel(const float* __restrict__ x,
                                                  float* __restrict__ out) {
    __shared__ __align__(16) float xg[16 * XG_CH];
    __shared__ __align__(16) float wt_s[KK_ * 64];

    int tid = threadIdx.x;
    int bid = blockIdx.x;
    int gs = bid & 3;
    int tile = (bid >> 2) & 63;
    int b = bid >> 8;
    int y0 = (tile >> 3) * 8, x0 = (tile & 7) * 8;
    const float* xb = x + (size_t)b * C_ * NPX_;

    // halo staging coords: 16 threads per channel, lane = xx
    int sc = tid >> 4, sl = tid & 15;
    int hgx = x0 + sl - 3;
    bool xok = (sl < 14) && (hgx >= 0) && (hgx < 64);

    // involution coords
    int ci = tid & 15, pxq = tid >> 4;
    int px0 = pxq * 4;
    int yloc = pxq >> 1, x0loc = (pxq & 1) * 4;

#pragma unroll 1
    for (int gi = 0; gi < 4; gi++) {
        int g = gs * 4 + gi;
        __syncthreads();

        // stage x group halo: division-free, predicated LDG
        {
            const float* xc = xb + (size_t)(g * GC_ + sc) * NPX_ + hgx;
            float* xgrow = xg + sc * XG_CH + sl;
#pragma unroll
            for (int rr = 0; rr < 14; rr++) {
                int gy = y0 + rr - 3;
                float v = (xok && gy >= 0 && gy < 64) ? xc[gy * 64] : 0.f;
                if (sl < 14) xgrow[rr * 16] = v;
            }
        }
        // stage wt slab (contiguous [49][64])
        {
            const float* src = g_wt + (((size_t)(b * 64 + tile)) * G_ + g) * KK_ * 64;
            for (int idx = tid; idx < KK_ * 64; idx += 256)
                wt_s[idx] = src[idx];
        }
        __syncthreads();

        // involution: 4 adjacent-x pixels x 1 channel per thread
        ull acc01 = 0ull, acc23 = 0ull;
        const float* xgc = xg + ci * XG_CH + yloc * 16 + x0loc;
        const float* wtp = wt_s + px0;
#pragma unroll
        for (int ky = 0; ky < 7; ky++) {
            const float* rowp = xgc + ky * 16;
            float4 rA = *(const float4*)rowp;
            float4 rB = *(const float4*)(rowp + 4);
            float2 rC = *(const float2*)(rowp + 8);
            float xr[10] = {rA.x, rA.y, rA.z, rA.w,
                            rB.x, rB.y, rB.z, rB.w,
                            rC.x, rC.y};
            ull xp[9];
#pragma unroll
            for (int j = 0; j < 9; j++) xp[j] = pk(xr[j], xr[j + 1]);
#pragma unroll
            for (int kx = 0; kx < 7; kx++) {
                ulonglong2 wq = *(const ulonglong2*)(wtp + (ky * 7 + kx) * 64);
                fma2(acc01, wq.x, xp[kx]);
                fma2(acc23, wq.y, xp[kx + 2]);
            }
        }
        float v0, v1, v2, v3;
        unpk(acc01, v0, v1);
        unpk(acc23, v2, v3);
        int gy = y0 + yloc, gx = x0 + x0loc;
        *(float4*)&out[((size_t)b * C_ + g * GC_ + ci) * NPX_ + gy * 64 + gx] =
            make_float4(v0, v1, v2, v3);
    }
}

// =================================================================
extern "C" void kernel_launch(void* const* d_in, const int* in_sizes, int n_in,
                              void* d_out, int out_size) {
    const float* x     = (const float*)d_in[0];
    const float* w1    = (const float*)d_in[1];
    const float* gamma = (const float*)d_in[2];
    const float* beta  = (const float*)d_in[3];
    const float* mean  = (const float*)d_in[4];
    const float* var   = (const float*)d_in[5];
    const float* w2    = (const float*)d_in[6];
    const float* b2    = (const float*)d_in[7];
    float* out = (float*)d_out;

    prep_kernel<<<224, 256>>>(w1, gamma, beta, mean, var, w2);
    conv1_kernel<<<BN_ * NPX_ / 32, 128>>>(x);
    conv2_kernel<<<BN_ * 64 * 4, 256>>>(b2);
    inv_kernel<<<BN_ * 64 * 4, 256>>>(x, out);
}

// round 13
// speedup vs baseline: 1.5659x; 1.0850x over previous
#include <cuda_runtime.h>

// Problem constants
#define BN_  4
#define C_   256
#define NPX_ 4096    // 64*64
#define O_   64
#define G_   16
#define GC_  16
#define GS_  4       // groups per block
#define KK_  49      // 7*7
#define KPAD 52      // padded k stride (mult of 4; w2s loads are broadcast)

typedef unsigned long long ull;

// --------- scratch (allocation-free: __device__ globals) ----------
__device__ __align__(16) float g_t[BN_ * NPX_ * O_];     // t, [b][px][o], 4 MB
__device__ __align__(16) float g_w1t[C_ * O_];           // [c][o], BN-folded
__device__ float g_b1[O_];
__device__ __align__(16) float g_w2t[G_ * O_ * KPAD];    // [g][o][k], zero-padded

// --------- f32x2 helpers (Blackwell packed fp32) ----------
__device__ __forceinline__ ull pk(float a, float b) {
    ull r; asm("mov.b64 %0,{%1,%2};" : "=l"(r) : "f"(a), "f"(b)); return r;
}
__device__ __forceinline__ ull dupf(float a) {
    ull r; asm("mov.b64 %0,{%1,%1};" : "=l"(r) : "f"(a)); return r;
}
__device__ __forceinline__ void fma2(ull& d, ull a, ull b) {
    asm("fma.rn.f32x2 %0,%1,%2,%0;" : "+l"(d) : "l"(a), "l"(b));
}
__device__ __forceinline__ void unpk(ull v, float& a, float& b) {
    asm("mov.b64 {%0,%1},%2;" : "=f"(a), "=f"(b) : "l"(v));
}

// =================================================================
// Prep: BN-fold + transpose w1 -> [c][o]; transpose w2 -> [g][o][k].
// =================================================================
__global__ __launch_bounds__(256) void prep_kernel(const float* __restrict__ w1,
                                                   const float* __restrict__ gamma,
                                                   const float* __restrict__ beta,
                                                   const float* __restrict__ mean,
                                                   const float* __restrict__ var,
                                                   const float* __restrict__ w2) {
    int tid = blockIdx.x * 256 + threadIdx.x;
    int nthr = gridDim.x * 256;

    for (int i = tid; i < C_ * O_; i += nthr) {
        int c = i >> 6, o = i & 63;
        float sc = gamma[o] * rsqrtf(var[o] + 1e-5f);
        g_w1t[i] = w1[(size_t)o * C_ + c] * sc;
    }
    if (tid < O_) {
        float sc = gamma[tid] * rsqrtf(var[tid] + 1e-5f);
        g_b1[tid] = beta[tid] - mean[tid] * sc;
    }
    for (int i = tid; i < G_ * KK_ * O_; i += nthr) {
        int o = i & 63;
        int gk = i >> 6;            // g*49 + k
        int g = gk / KK_, k = gk - g * KK_;
        g_w2t[((size_t)(g * O_ + o)) * KPAD + k] = w2[i];
    }
    for (int i = tid; i < G_ * O_ * (KPAD - KK_); i += nthr) {
        int kk = i % (KPAD - KK_);
        int go = i / (KPAD - KK_);
        g_w2t[(size_t)go * KPAD + KK_ + kk] = 0.f;
    }
}

// =================================================================
// conv1: t[bpx][o] = relu(sum_c w1t[c][o]*x + b1[o])
// Block: 128 threads, 32 px x 64 o, grid 512. Thread: 2px x 8o.
// =================================================================
#define WS1 68
__global__ __launch_bounds__(128) void conv1_kernel(const float* __restrict__ x) {
    __shared__ __align__(16) float xs[32 * 32];   // [c][px]
    __shared__ __align__(16) float ws[32 * WS1];  // [c][o] (+pad)

    int tid = threadIdx.x;
    int bpx0 = blockIdx.x * 32;
    const float* xb = x + (size_t)(bpx0 / NPX_) * C_ * NPX_ + (bpx0 % NPX_);

    int to = tid & 7, tp = tid >> 3;
    int p0 = tp * 2, o0 = to * 8;

    ull acc0[4] = {0, 0, 0, 0};
    ull acc1[4] = {0, 0, 0, 0};

    for (int cc = 0; cc < C_; cc += 32) {
        __syncthreads();
#pragma unroll
        for (int i = 0; i < 8; i++) {
            int idx = tid + i * 128;
            int c = idx >> 5, low = idx & 31;
            xs[c * 32 + low] = xb[(size_t)(cc + c) * NPX_ + low];
        }
#pragma unroll
        for (int i = 0; i < 16; i++) {
            int idx = tid + i * 128;
            int c = idx >> 6, o = idx & 63;
            ws[c * WS1 + o] = g_w1t[(cc + c) * O_ + o];
        }
        __syncthreads();
#pragma unroll
        for (int c = 0; c < 32; c++) {
            float2 xv = *(const float2*)&xs[c * 32 + p0];
            ull x0d = dupf(xv.x), x1d = dupf(xv.y);
            ulonglong2 wA = *(const ulonglong2*)&ws[c * WS1 + o0];
            ulonglong2 wB = *(const ulonglong2*)&ws[c * WS1 + o0 + 4];
            fma2(acc0[0], wA.x, x0d); fma2(acc0[1], wA.y, x0d);
            fma2(acc0[2], wB.x, x0d); fma2(acc0[3], wB.y, x0d);
            fma2(acc1[0], wA.x, x1d); fma2(acc1[1], wA.y, x1d);
            fma2(acc1[2], wB.x, x1d); fma2(acc1[3], wB.y, x1d);
        }
    }

#pragma unroll
    for (int p = 0; p < 2; p++) {
        ull* acc = p ? acc1 : acc0;
        float v[8];
#pragma unroll
        for (int j = 0; j < 4; j++) {
            float a, b;
            unpk(acc[j], a, b);
            v[2 * j]     = fmaxf(a + g_b1[o0 + 2 * j], 0.f);
            v[2 * j + 1] = fmaxf(b + g_b1[o0 + 2 * j + 1], 0.f);
        }
        float* dst = &g_t[(size_t)(bpx0 + p0 + p) * O_ + o0];
        *(float4*)dst       = make_float4(v[0], v[1], v[2], v[3]);
        *(float4*)(dst + 4) = make_float4(v[4], v[5], v[6], v[7]);
    }
}

// =================================================================
// Fused conv2 + involution, 4 groups/block (grid = 4*64*4 = 1024).
// smem = t_s 16.25K + xg 14.25K + w2s 13K + wt_s 12.25K = 55.75KB
//   -> 4 blocks/SM (4*(57088+1024) = 232448 <= 233472).
//   - conv2: wt[px][k] = sum_o w2s[o][k]*t_s[px][o] + b2  (f32x2 k-pairs)
//   - involution: out[c] = sum_k wt[k]*x[c, shifted]      (f32x2 px-pairs)
// =================================================================
#define TS_STRIDE 65           // t_s row stride (bank-conflict-free)
#define XG_CH 228              // xg channel stride: footprint 13*16+14=222,
                               //   ==4 mod 32, 16B-aligned
#define SM_T   0
#define SM_XG  (64 * TS_STRIDE)
#define SM_W2  (SM_XG + 16 * XG_CH)
#define SM_WT  (SM_W2 + 64 * KPAD)
#define SM_TOT (SM_WT + KK_ * 64)
#define SMEM_BYTES (SM_TOT * 4)

__global__ __launch_bounds__(256) void inv_kernel(const float* __restrict__ x,
                                                  const float* __restrict__ b2,
                                                  float* __restrict__ out) {
    extern __shared__ __align__(16) float sm[];
    float* t_s  = sm + SM_T;    // [64px][65]
    float* xg   = sm + SM_XG;   // [16c][228]
    float* w2s  = sm + SM_W2;   // [64o][52k]
    float* wt_s = sm + SM_WT;   // [49k][64px]

    int tid = threadIdx.x;
    int bid = blockIdx.x;
    int gs = bid & (GS_ - 1);
    int tile = (bid >> 2) & 63;
    int b = bid >> 8;
    int y0 = (tile >> 3) * 8, x0 = (tile & 7) * 8;
    const float* xb = x + (size_t)b * C_ * NPX_;

    // stage t tile (64 px x 64 o), coalesced over o, stride-1 stores
#pragma unroll
    for (int i = 0; i < 16; i++) {
        int idx = tid + i * 256;
        int pxl = idx >> 6, o = idx & 63;
        int r = pxl >> 3, cx = pxl & 7;
        t_s[pxl * TS_STRIDE + o] =
            g_t[((size_t)b * NPX_ + (y0 + r) * 64 + (x0 + cx)) * O_ + o];
    }

    // conv2 thread coords: kq 0..7 (active <7), pq 0..31 -> pixels pq, pq+32
    int kq = tid >> 5, pq = tid & 31;
    // involution thread coords: ci in LOW bits (wt loads broadcast per warp)
    int ci = tid & 15, pxq = tid >> 4;
    int px0 = pxq * 4;
    int yloc = pxq >> 1, x0loc = (pxq & 1) * 4;

#pragma unroll 1
    for (int gi = 0; gi < GS_; gi++) {
        int g = gs * GS_ + gi;
        __syncthreads();  // prev involution done with xg/wt_s; t_s staged (gi==0)

        // stage x group halo (14x14 per channel, zero-padded)
        for (int idx = tid; idx < 16 * 196; idx += 256) {
            int c = idx / 196, rem = idx - c * 196;
            int rr = rem / 14, xx = rem - rr * 14;
            int gy = y0 + rr - 3, gx = x0 + xx - 3;
            float v = 0.f;
            if (gy >= 0 && gy < 64 && gx >= 0 && gx < 64)
                v = xb[(size_t)(g * GC_ + c) * NPX_ + gy * 64 + gx];
            xg[c * XG_CH + rr * 16 + xx] = v;
        }
        // stage w2 slice (pre-transposed, stride-1 copy; 3328 = 13*256)
        {
            const float* src = g_w2t + (size_t)g * O_ * KPAD;
#pragma unroll
            for (int i = 0; i < 13; i++)
                w2s[tid + i * 256] = src[tid + i * 256];
        }
        __syncthreads();

        // ---- conv2: 2 pixels x 8 k per thread, f32x2 over k-pairs ----
        if (kq < 7) {
            int k0 = kq * 8;
            ull accA[4], accB[4];
#pragma unroll
            for (int j = 0; j < 4; j++) {
                int ka = k0 + 2 * j, kb = ka + 1;
                float ba = (ka < KK_) ? b2[g * KK_ + ka] : 0.f;
                float bb = (kb < KK_) ? b2[g * KK_ + kb] : 0.f;
                accA[j] = pk(ba, bb);
                accB[j] = accA[j];
            }
            const float* w2p = w2s + k0;
            const float* tp0 = t_s + pq * TS_STRIDE;
            const float* tp1 = t_s + (pq + 32) * TS_STRIDE;
#pragma unroll 8
            for (int o = 0; o < 64; o++) {
                ulonglong2 w01 = *(const ulonglong2*)(w2p + o * KPAD);
                ulonglong2 w23 = *(const ulonglong2*)(w2p + o * KPAD + 4);
                ull da = dupf(tp0[o]);
                ull db = dupf(tp1[o]);
                fma2(accA[0], w01.x, da); fma2(accA[1], w01.y, da);
                fma2(accA[2], w23.x, da); fma2(accA[3], w23.y, da);
                fma2(accB[0], w01.x, db); fma2(accB[1], w01.y, db);
                fma2(accB[2], w23.x, db); fma2(accB[3], w23.y, db);
            }
#pragma unroll
            for (int j = 0; j < 4; j++) {
                int ka = k0 + 2 * j, kb = ka + 1;
                float a0, a1, b0, b1;
                unpk(accA[j], a0, a1);
                unpk(accB[j], b0, b1);
                if (ka < KK_) {
                    wt_s[ka * 64 + pq]      = a0;
                    wt_s[ka * 64 + pq + 32] = b0;
                }
                if (kb < KK_) {
                    wt_s[kb * 64 + pq]      = a1;
                    wt_s[kb * 64 + pq + 32] = b1;
                }
            }
        }
        __syncthreads();

        // ---- involution: 4 adjacent-x pixels x 1 channel per thread ----
        {
            ull acc01 = 0ull, acc23 = 0ull;
            const float* xgc = xg + ci * XG_CH + yloc * 16 + x0loc;
            const float* wtp = wt_s + px0;
#pragma unroll
            for (int ky = 0; ky < 7; ky++) {
                const float* rowp = xgc + ky * 16;
                float4 rA = *(const float4*)rowp;
                float4 rB = *(const float4*)(rowp + 4);
                float2 rC = *(const float2*)(rowp + 8);
                float xr[10] = {rA.x, rA.y, rA.z, rA.w,
                                rB.x, rB.y, rB.z, rB.w,
                                rC.x, rC.y};
                ull xp[9];
#pragma unroll
                for (int j = 0; j < 9; j++) xp[j] = pk(xr[j], xr[j + 1]);
#pragma unroll
                for (int kx = 0; kx < 7; kx++) {
                    ulonglong2 wq = *(const ulonglong2*)(wtp + (ky * 7 + kx) * 64);
                    fma2(acc01, wq.x, xp[kx]);
                    fma2(acc23, wq.y, xp[kx + 2]);
                }
            }
            float v0, v1, v2, v3;
            unpk(acc01, v0, v1);
            unpk(acc23, v2, v3);
            int gy = y0 + yloc, gx = x0 + x0loc;
            *(float4*)&out[((size_t)b * C_ + g * GC_ + ci) * NPX_ + gy * 64 + gx] =
                make_float4(v0, v1, v2, v3);
        }
    }
}

// =================================================================
extern "C" void kernel_launch(void* const* d_in, const int* in_sizes, int n_in,
                              void* d_out, int out_size) {
    const float* x     = (const float*)d_in[0];
    const float* w1    = (const float*)d_in[1];
    const float* gamma = (const float*)d_in[2];
    const float* beta  = (const float*)d_in[3];
    const float* mean  = (const float*)d_in[4];
    const float* var   = (const float*)d_in[5];
    const float* w2    = (const float*)d_in[6];
    const float* b2    = (const float*)d_in[7];
    float* out = (float*)d_out;

    cudaFuncSetAttribute(inv_kernel, cudaFuncAttributeMaxDynamicSharedMemorySize,
                         SMEM_BYTES);

    prep_kernel<<<224, 256>>>(w1, gamma, beta, mean, var, w2);
    conv1_kernel<<<BN_ * NPX_ / 32, 128>>>(x);
    inv_kernel<<<BN_ * 64 * GS_, 256, SMEM_BYTES>>>(x, b2, out);
}

// round 15
// speedup vs baseline: 1.6101x; 1.0282x over previous
#include <cuda_runtime.h>

// Problem constants
#define BN_  4
#define C_   256
#define NPX_ 4096    // 64*64
#define O_   64
#define G_   16
#define GC_  16
#define GS_  4       // groups per block
#define KK_  49      // 7*7
#define KPAD 52      // padded k stride (mult of 4; w2s loads are broadcast)

typedef unsigned long long ull;

// --------- scratch (allocation-free: __device__ globals) ----------
__device__ __align__(16) float g_t[BN_ * NPX_ * O_];     // t, [b][px][o], 4 MB
__device__ __align__(16) float g_w1t[C_ * O_];           // [c][o], BN-folded
__device__ float g_b1[O_];
__device__ __align__(16) float g_w2t[G_ * O_ * KPAD];    // [g][o][k], zero-padded

// --------- f32x2 helpers (Blackwell packed fp32) ----------
__device__ __forceinline__ ull pk(float a, float b) {
    ull r; asm("mov.b64 %0,{%1,%2};" : "=l"(r) : "f"(a), "f"(b)); return r;
}
__device__ __forceinline__ ull dupf(float a) {
    ull r; asm("mov.b64 %0,{%1,%1};" : "=l"(r) : "f"(a)); return r;
}
__device__ __forceinline__ void fma2(ull& d, ull a, ull b) {
    asm("fma.rn.f32x2 %0,%1,%2,%0;" : "+l"(d) : "l"(a), "l"(b));
}
__device__ __forceinline__ void unpk(ull v, float& a, float& b) {
    asm("mov.b64 {%0,%1},%2;" : "=f"(a), "=f"(b) : "l"(v));
}

// =================================================================
// Prep: BN-fold + transpose w1 -> [c][o]; transpose w2 -> [g][o][k].
// =================================================================
__global__ __launch_bounds__(256) void prep_kernel(const float* __restrict__ w1,
                                                   const float* __restrict__ gamma,
                                                   const float* __restrict__ beta,
                                                   const float* __restrict__ mean,
                                                   const float* __restrict__ var,
                                                   const float* __restrict__ w2) {
    int tid = blockIdx.x * 256 + threadIdx.x;
    int nthr = gridDim.x * 256;

    for (int i = tid; i < C_ * O_; i += nthr) {
        int c = i >> 6, o = i & 63;
        float sc = gamma[o] * rsqrtf(var[o] + 1e-5f);
        g_w1t[i] = w1[(size_t)o * C_ + c] * sc;
    }
    if (tid < O_) {
        float sc = gamma[tid] * rsqrtf(var[tid] + 1e-5f);
        g_b1[tid] = beta[tid] - mean[tid] * sc;
    }
    for (int i = tid; i < G_ * KK_ * O_; i += nthr) {
        int o = i & 63;
        int gk = i >> 6;            // g*49 + k
        int g = gk / KK_, k = gk - g * KK_;
        g_w2t[((size_t)(g * O_ + o)) * KPAD + k] = w2[i];
    }
    for (int i = tid; i < G_ * O_ * (KPAD - KK_); i += nthr) {
        int kk = i % (KPAD - KK_);
        int go = i / (KPAD - KK_);
        g_w2t[(size_t)go * KPAD + KK_ + kk] = 0.f;
    }
}

// =================================================================
// conv1: t[bpx][o] = relu(sum_c w1t[c][o]*x + b1[o])
// Block: 128 threads, 32 px x 64 o, grid 512. Thread: 2px x 8o.
// =================================================================
#define WS1 68
__global__ __launch_bounds__(128) void conv1_kernel(const float* __restrict__ x) {
    __shared__ __align__(16) float xs[32 * 32];   // [c][px]
    __shared__ __align__(16) float ws[32 * WS1];  // [c][o] (+pad)

    int tid = threadIdx.x;
    int bpx0 = blockIdx.x * 32;
    const float* xb = x + (size_t)(bpx0 / NPX_) * C_ * NPX_ + (bpx0 % NPX_);

    int to = tid & 7, tp = tid >> 3;
    int p0 = tp * 2, o0 = to * 8;

    ull acc0[4] = {0, 0, 0, 0};
    ull acc1[4] = {0, 0, 0, 0};

    for (int cc = 0; cc < C_; cc += 32) {
        __syncthreads();
#pragma unroll
        for (int i = 0; i < 8; i++) {
            int idx = tid + i * 128;
            int c = idx >> 5, low = idx & 31;
            xs[c * 32 + low] = xb[(size_t)(cc + c) * NPX_ + low];
        }
#pragma unroll
        for (int i = 0; i < 16; i++) {
            int idx = tid + i * 128;
            int c = idx >> 6, o = idx & 63;
            ws[c * WS1 + o] = g_w1t[(cc + c) * O_ + o];
        }
        __syncthreads();
#pragma unroll
        for (int c = 0; c < 32; c++) {
            float2 xv = *(const float2*)&xs[c * 32 + p0];
            ull x0d = dupf(xv.x), x1d = dupf(xv.y);
            ulonglong2 wA = *(const ulonglong2*)&ws[c * WS1 + o0];
            ulonglong2 wB = *(const ulonglong2*)&ws[c * WS1 + o0 + 4];
            fma2(acc0[0], wA.x, x0d); fma2(acc0[1], wA.y, x0d);
            fma2(acc0[2], wB.x, x0d); fma2(acc0[3], wB.y, x0d);
            fma2(acc1[0], wA.x, x1d); fma2(acc1[1], wA.y, x1d);
            fma2(acc1[2], wB.x, x1d); fma2(acc1[3], wB.y, x1d);
        }
    }

#pragma unroll
    for (int p = 0; p < 2; p++) {
        ull* acc = p ? acc1 : acc0;
        float v[8];
#pragma unroll
        for (int j = 0; j < 4; j++) {
            float a, b;
            unpk(acc[j], a, b);
            v[2 * j]     = fmaxf(a + g_b1[o0 + 2 * j], 0.f);
            v[2 * j + 1] = fmaxf(b + g_b1[o0 + 2 * j + 1], 0.f);
        }
        float* dst = &g_t[(size_t)(bpx0 + p0 + p) * O_ + o0];
        *(float4*)dst       = make_float4(v[0], v[1], v[2], v[3]);
        *(float4*)(dst + 4) = make_float4(v[4], v[5], v[6], v[7]);
    }
}

// =================================================================
// Fused conv2 + involution, 4 groups/block (grid = 4*64*4 = 1024).
// smem 55.75KB -> 4 blocks/SM. Warp-6 conv2 trimmed to its one live
// k-pair; warps 0-5 store unconditionally (k <= 47 < 49 always).
// =================================================================
#define TS_STRIDE 65           // t_s row stride (bank-conflict-free)
#define XG_CH 228              // xg channel stride: footprint 222, ==4 mod 32
#define SM_T   0
#define SM_XG  (64 * TS_STRIDE)
#define SM_W2  (SM_XG + 16 * XG_CH)
#define SM_WT  (SM_W2 + 64 * KPAD)
#define SM_TOT (SM_WT + KK_ * 64)
#define SMEM_BYTES (SM_TOT * 4)

__global__ __launch_bounds__(256) void inv_kernel(const float* __restrict__ x,
                                                  const float* __restrict__ b2,
                                                  float* __restrict__ out) {
    extern __shared__ __align__(16) float sm[];
    float* t_s  = sm + SM_T;    // [64px][65]
    float* xg   = sm + SM_XG;   // [16c][228]
    float* w2s  = sm + SM_W2;   // [64o][52k]
    float* wt_s = sm + SM_WT;   // [49k][64px]

    int tid = threadIdx.x;
    int bid = blockIdx.x;
    int gs = bid & (GS_ - 1);
    int tile = (bid >> 2) & 63;
    int b = bid >> 8;
    int y0 = (tile >> 3) * 8, x0 = (tile & 7) * 8;
    const float* xb = x + (size_t)b * C_ * NPX_;

    // interior tiles (36/64): halo never leaves the image
    bool interior = (y0 >= 8) && (y0 <= 48) && (x0 >= 8) && (x0 <= 48);

    // stage t tile (64 px x 64 o)
#pragma unroll
    for (int i = 0; i < 16; i++) {
        int idx = tid + i * 256;
        int pxl = idx >> 6, o = idx & 63;
        int r = pxl >> 3, cx = pxl & 7;
        t_s[pxl * TS_STRIDE + o] =
            g_t[((size_t)b * NPX_ + (y0 + r) * 64 + (x0 + cx)) * O_ + o];
    }

    // conv2 thread coords
    int kq = tid >> 5, pq = tid & 31;
    // involution thread coords: ci in LOW bits (wt loads broadcast per warp)
    int ci = tid & 15, pxq = tid >> 4;
    int px0 = pxq * 4;
    int yloc = pxq >> 1, x0loc = (pxq & 1) * 4;

#pragma unroll 1
    for (int gi = 0; gi < GS_; gi++) {
        int g = gs * GS_ + gi;
        __syncthreads();  // prev involution done with xg/wt_s; t_s staged (gi==0)

        // stage x group halo (14x14 per channel)
        if (interior) {
            for (int idx = tid; idx < 16 * 196; idx += 256) {
                int c = idx / 196, rem = idx - c * 196;
                int rr = rem / 14, xx = rem - rr * 14;
                xg[c * XG_CH + rr * 16 + xx] =
                    xb[(size_t)(g * GC_ + c) * NPX_ + (y0 + rr - 3) * 64 + (x0 + xx - 3)];
            }
        } else {
            for (int idx = tid; idx < 16 * 196; idx += 256) {
                int c = idx / 196, rem = idx - c * 196;
                int rr = rem / 14, xx = rem - rr * 14;
                int gy = y0 + rr - 3, gx = x0 + xx - 3;
                float v = 0.f;
                if (gy >= 0 && gy < 64 && gx >= 0 && gx < 64)
                    v = xb[(size_t)(g * GC_ + c) * NPX_ + gy * 64 + gx];
                xg[c * XG_CH + rr * 16 + xx] = v;
            }
        }
        // stage w2 slice (pre-transposed, stride-1 copy; 3328 = 13*256)
        {
            const float* src = g_w2t + (size_t)g * O_ * KPAD;
#pragma unroll
            for (int i = 0; i < 13; i++)
                w2s[tid + i * 256] = src[tid + i * 256];
        }
        __syncthreads();

        // ---- conv2 ----
        if (kq < 6) {
            // full path: 8 k (4 pairs) x 2 px, all k <= 47 live
            int k0 = kq * 8;
            ull accA[4], accB[4];
#pragma unroll
            for (int j = 0; j < 4; j++) {
                accA[j] = pk(b2[g * KK_ + k0 + 2 * j], b2[g * KK_ + k0 + 2 * j + 1]);
                accB[j] = accA[j];
            }
            const float* w2p = w2s + k0;
            const float* tp0 = t_s + pq * TS_STRIDE;
            const float* tp1 = t_s + (pq + 32) * TS_STRIDE;
#pragma unroll 8
            for (int o = 0; o < 64; o++) {
                ulonglong2 w01 = *(const ulonglong2*)(w2p + o * KPAD);
                ulonglong2 w23 = *(const ulonglong2*)(w2p + o * KPAD + 4);
                ull da = dupf(tp0[o]);
                ull db = dupf(tp1[o]);
                fma2(accA[0], w01.x, da); fma2(accA[1], w01.y, da);
                fma2(accA[2], w23.x, da); fma2(accA[3], w23.y, da);
                fma2(accB[0], w01.x, db); fma2(accB[1], w01.y, db);
                fma2(accB[2], w23.x, db); fma2(accB[3], w23.y, db);
            }
#pragma unroll
            for (int j = 0; j < 4; j++) {
                int ka = k0 + 2 * j;
                float a0, a1, b0, b1;
                unpk(accA[j], a0, a1);
                unpk(accB[j], b0, b1);
                wt_s[ka * 64 + pq]            = a0;
                wt_s[(ka + 1) * 64 + pq]      = a1;
                wt_s[ka * 64 + pq + 32]       = b0;
                wt_s[(ka + 1) * 64 + pq + 32] = b1;
            }
        } else if (kq == 6) {
            // trimmed path: only k=48 is live (k=49 rides the pair, w2s pad=0)
            ull accA = pk(b2[g * KK_ + 48], 0.f);
            ull accB = accA;
            const float* w2p = w2s + 48;
            const float* tp0 = t_s + pq * TS_STRIDE;
            const float* tp1 = t_s + (pq + 32) * TS_STRIDE;
#pragma unroll 8
            for (int o = 0; o < 64; o++) {
                ull w01 = *(const ull*)(w2p + o * KPAD);
                fma2(accA, w01, dupf(tp0[o]));
                fma2(accB, w01, dupf(tp1[o]));
            }
            float a0, a1, b0, b1;
            unpk(accA, a0, a1);
            unpk(accB, b0, b1);
            wt_s[48 * 64 + pq]      = a0;
            wt_s[48 * 64 + pq + 32] = b0;
        }
        __syncthreads();

        // ---- involution: 4 adjacent-x pixels x 1 channel per thread ----
        {
            ull acc01 = 0ull, acc23 = 0ull;
            const float* xgc = xg + ci * XG_CH + yloc * 16 + x0loc;
            const float* wtp = wt_s + px0;
#pragma unroll
            for (int ky = 0; ky < 7; ky++) {
                const float* rowp = xgc + ky * 16;
                float4 rA = *(const float4*)rowp;
                float4 rB = *(const float4*)(rowp + 4);
                float2 rC = *(const float2*)(rowp + 8);
                float xr[10] = {rA.x, rA.y, rA.z, rA.w,
                                rB.x, rB.y, rB.z, rB.w,
                                rC.x, rC.y};
                ull xp[9];
#pragma unroll
                for (int j = 0; j < 9; j++) xp[j] = pk(xr[j], xr[j + 1]);
#pragma unroll
                for (int kx = 0; kx < 7; kx++) {
                    ulonglong2 wq = *(const ulonglong2*)(wtp + (ky * 7 + kx) * 64);
                    fma2(acc01, wq.x, xp[kx]);
                    fma2(acc23, wq.y, xp[kx + 2]);
                }
            }
            float v0, v1, v2, v3;
            unpk(acc01, v0, v1);
            unpk(acc23, v2, v3);
            int gy = y0 + yloc, gx = x0 + x0loc;
            *(float4*)&out[((size_t)b * C_ + g * GC_ + ci) * NPX_ + gy * 64 + gx] =
                make_float4(v0, v1, v2, v3);
        }
    }
}

// =================================================================
extern "C" void kernel_launch(void* const* d_in, const int* in_sizes, int n_in,
                              void* d_out, int out_size) {
    const float* x     = (const float*)d_in[0];
    const float* w1    = (const float*)d_in[1];
    const float* gamma = (const float*)d_in[2];
    const float* beta  = (const float*)d_in[3];
    const float* mean  = (const float*)d_in[4];
    const float* var   = (const float*)d_in[5];
    const float* w2    = (const float*)d_in[6];
    const float* b2    = (const float*)d_in[7];
    float* out = (float*)d_out;

    cudaFuncSetAttribute(inv_kernel, cudaFuncAttributeMaxDynamicSharedMemorySize,
                         SMEM_BYTES);

    prep_kernel<<<224, 256>>>(w1, gamma, beta, mean, var, w2);
    conv1_kernel<<<BN_ * NPX_ / 32, 128>>>(x);
    inv_kernel<<<BN_ * 64 * GS_, 256, SMEM_BYTES>>>(x, b2, out);
}